// round 15
// baseline (speedup 1.0000x reference)
#include <cuda_runtime.h>
#include <cuda_fp16.h>
#include <cuda_bf16.h>

// Problem constants
#define BB 8
#define SS 1024
#define DD 1024
#define HH 16
#define HD 64
#define MROWS (BB*SS)     // 8192

// Scratch (device globals; no allocation allowed)
__device__ float g_Q[(size_t)BB*HH*SS*HD];
__device__ float g_K[(size_t)BB*HH*SS*HD];
__device__ float g_V[(size_t)BB*HH*SS*HD];
__device__ float g_ctx[(size_t)BB*SS*DD];

__device__ __forceinline__ unsigned f2tf(float f) {
    unsigned u;
    asm("cvt.rna.tf32.f32 %0, %1;" : "=r"(u) : "f"(f));
    return u;
}

// pack two floats into f16x2 {lo, hi}
__device__ __forceinline__ unsigned pack_h2(float lo, float hi) {
    unsigned u;
    asm("cvt.rn.f16x2.f32 %0, %1, %2;" : "=r"(u) : "f"(hi), "f"(lo));
    return u;
}

__device__ __forceinline__ void mma_tf32(float c[4], const unsigned a[4], const unsigned b[2]) {
    asm volatile(
        "mma.sync.aligned.m16n8k8.row.col.f32.tf32.tf32.f32 "
        "{%0,%1,%2,%3}, {%4,%5,%6,%7}, {%8,%9}, {%0,%1,%2,%3};"
        : "+f"(c[0]), "+f"(c[1]), "+f"(c[2]), "+f"(c[3])
        : "r"(a[0]), "r"(a[1]), "r"(a[2]), "r"(a[3]),
          "r"(b[0]), "r"(b[1]));
}

__device__ __forceinline__ void mma_f16(float c[4], const unsigned a[4], const unsigned b[2]) {
    asm volatile(
        "mma.sync.aligned.m16n8k16.row.col.f32.f16.f16.f32 "
        "{%0,%1,%2,%3}, {%4,%5,%6,%7}, {%8,%9}, {%0,%1,%2,%3};"
        : "+f"(c[0]), "+f"(c[1]), "+f"(c[2]), "+f"(c[3])
        : "r"(a[0]), "r"(a[1]), "r"(a[2]), "r"(a[3]),
          "r"(b[0]), "r"(b[1]));
}

__device__ __forceinline__ void ldsm_x4(unsigned r[4], unsigned addr) {
    asm volatile(
        "ldmatrix.sync.aligned.m8n8.x4.shared.b16 {%0,%1,%2,%3}, [%4];"
        : "=r"(r[0]), "=r"(r[1]), "=r"(r[2]), "=r"(r[3]) : "r"(addr));
}

__device__ __forceinline__ void ldsm_x4_trans(unsigned r[4], unsigned addr) {
    asm volatile(
        "ldmatrix.sync.aligned.m8n8.x4.trans.shared.b16 {%0,%1,%2,%3}, [%4];"
        : "=r"(r[0]), "=r"(r[1]), "=r"(r[2]), "=r"(r[3]) : "r"(addr));
}

// ---------------------------------------------------------------------------
// fp16 GEMM body, double-buffered SMEM pipeline.
// Tile BM=BN=128, BK=32; 256 threads = 8 warps (warp 64x32).
// Xs [m][k] halves, stride 40; Ws [k][n] halves, stride 136 (conflict-free).
// Per k-tile: LDG(next) -> MMA(cur) -> STS(next^buf) -> ONE barrier.
// ---------------------------------------------------------------------------
struct GemmSmem {
    __half Xs[2][128][40];
    __half Ws[2][32][136];
};
#define XBUF_BYTES (128 * 40 * 2)
#define WBUF_BYTES (32 * 136 * 2)

struct GemmCtx {
    int xr, xc, wr, wc;
    unsigned aBase[4], bBase;
};

__device__ __forceinline__ void g_ldg(
    const float* __restrict__ X, const float* __restrict__ W,
    const GemmCtx& c, int m0, int n0, int kt, float4 px[4], float4 pw[4])
{
    const int k0 = kt * 32;
    #pragma unroll
    for (int i = 0; i < 4; i++) {
        px[i] = *(const float4*)(X + (size_t)(m0 + c.xr) * DD + k0 + c.xc + i * 4);
        pw[i] = *(const float4*)(W + (size_t)(k0 + c.wr) * DD + n0 + c.wc + i * 4);
    }
}

template<int BUF>
__device__ __forceinline__ void g_sts(
    GemmSmem& sm, const GemmCtx& c, const float4 px[4], const float4 pw[4])
{
    uint4 u;
    u.x = pack_h2(px[0].x, px[0].y); u.y = pack_h2(px[0].z, px[0].w);
    u.z = pack_h2(px[1].x, px[1].y); u.w = pack_h2(px[1].z, px[1].w);
    *(uint4*)&sm.Xs[BUF][c.xr][c.xc] = u;
    u.x = pack_h2(px[2].x, px[2].y); u.y = pack_h2(px[2].z, px[2].w);
    u.z = pack_h2(px[3].x, px[3].y); u.w = pack_h2(px[3].z, px[3].w);
    *(uint4*)&sm.Xs[BUF][c.xr][c.xc + 8] = u;
    u.x = pack_h2(pw[0].x, pw[0].y); u.y = pack_h2(pw[0].z, pw[0].w);
    u.z = pack_h2(pw[1].x, pw[1].y); u.w = pack_h2(pw[1].z, pw[1].w);
    *(uint4*)&sm.Ws[BUF][c.wr][c.wc] = u;
    u.x = pack_h2(pw[2].x, pw[2].y); u.y = pack_h2(pw[2].z, pw[2].w);
    u.z = pack_h2(pw[3].x, pw[3].y); u.w = pack_h2(pw[3].z, pw[3].w);
    *(uint4*)&sm.Ws[BUF][c.wr][c.wc + 8] = u;
}

template<int BUF>
__device__ __forceinline__ void g_mma(const GemmCtx& c, float acc[4][4][4])
{
    const unsigned xoff = BUF * XBUF_BYTES;
    const unsigned woff = BUF * WBUF_BYTES;
    #pragma unroll
    for (int ks = 0; ks < 2; ks++) {
        unsigned a[4][4], b[4][2];
        #pragma unroll
        for (int mt = 0; mt < 4; mt++)
            ldsm_x4(a[mt], c.aBase[mt] + xoff + (unsigned)(ks * 32));
        {
            unsigned r[4];
            ldsm_x4_trans(r, c.bBase + woff + (unsigned)(ks * 16 * 272));
            b[0][0] = r[0]; b[0][1] = r[1];
            b[1][0] = r[2]; b[1][1] = r[3];
            ldsm_x4_trans(r, c.bBase + woff + (unsigned)(ks * 16 * 272 + 32));
            b[2][0] = r[0]; b[2][1] = r[1];
            b[3][0] = r[2]; b[3][1] = r[3];
        }
        #pragma unroll
        for (int mt = 0; mt < 4; mt++)
            #pragma unroll
            for (int nt = 0; nt < 4; nt++)
                mma_f16(acc[mt][nt], a[mt], b[nt]);
    }
}

__device__ __forceinline__ void gemm_body(
    const float* __restrict__ X, const float* __restrict__ W,
    GemmSmem& sm, float acc[4][4][4], int m0, int n0)
{
    const int tid  = threadIdx.x;
    const int lane = tid & 31;
    const int warp = tid >> 5;
    const int wm   = warp & 1;
    const int wn   = warp >> 1;

    GemmCtx c;
    c.xr = tid >> 1;
    c.xc = (tid & 1) * 16;
    c.wr = tid >> 3;
    c.wc = (tid & 7) * 16;
    {
        unsigned xs0 = (unsigned)__cvta_generic_to_shared(&sm.Xs[0][0][0]);
        unsigned ws0 = (unsigned)__cvta_generic_to_shared(&sm.Ws[0][0][0]);
        #pragma unroll
        for (int mt = 0; mt < 4; mt++) {
            int row = wm * 64 + mt * 16 + (lane & 15);
            c.aBase[mt] = xs0 + (unsigned)(row * 80 + (lane >> 4) * 16);
        }
        int brow = (lane & 7) + ((lane >> 3) & 1) * 8;
        c.bBase = ws0 + (unsigned)(brow * 272 + (wn * 32 + (lane >> 4) * 8) * 2);
    }

    float4 px[4], pw[4];
    g_ldg(X, W, c, m0, n0, 0, px, pw);
    g_sts<0>(sm, c, px, pw);
    __syncthreads();

    #pragma unroll 1
    for (int kt = 0; kt < 32; kt += 2) {
        // sub-iter A: compute buf0 (tile kt), pipeline tile kt+1 into buf1
        if (kt + 1 < 32) g_ldg(X, W, c, m0, n0, kt + 1, px, pw);
        g_mma<0>(c, acc);
        if (kt + 1 < 32) g_sts<1>(sm, c, px, pw);
        __syncthreads();
        // sub-iter B: compute buf1 (tile kt+1), pipeline tile kt+2 into buf0
        if (kt + 2 < 32) g_ldg(X, W, c, m0, n0, kt + 2, px, pw);
        if (kt + 1 < 32) g_mma<1>(c, acc);
        if (kt + 2 < 32) g_sts<0>(sm, c, px, pw);
        __syncthreads();
    }
}

// Fused Q/K/V projection: z = blockIdx.z selects weights/bias/epilogue.
__global__ void __launch_bounds__(256, 2) gemm_qkv(
    const float* __restrict__ X,
    const float* __restrict__ Wq, const float* __restrict__ Wk, const float* __restrict__ Wv,
    const float* __restrict__ bq, const float* __restrict__ bk, const float* __restrict__ bv,
    const float* __restrict__ rel,
    float* __restrict__ Qo, float* __restrict__ Ko, float* __restrict__ Vo)
{
    __shared__ GemmSmem sm;

    const int z = blockIdx.z;
    const float* W    = (z == 0) ? Wq : (z == 1) ? Wk : Wv;
    const float* bias = (z == 0) ? bq : (z == 1) ? bk : bv;
    float*       Y    = (z == 0) ? Qo : (z == 1) ? Ko : Vo;

    const int tid  = threadIdx.x;
    const int warp = tid >> 5;
    const int lane = tid & 31;
    const int g    = lane >> 2;
    const int t4   = lane & 3;
    const int wm   = warp & 1;
    const int wn   = warp >> 1;
    const int m0   = blockIdx.y * 128;
    const int n0   = blockIdx.x * 128;

    float acc[4][4][4];
    #pragma unroll
    for (int mt = 0; mt < 4; mt++)
        #pragma unroll
        for (int nt = 0; nt < 4; nt++)
            #pragma unroll
            for (int r = 0; r < 4; r++) acc[mt][nt][r] = 0.f;

    gemm_body(X, W, sm, acc, m0, n0);

    const float scale = 0.125f;   // HD^-0.5
    #pragma unroll
    for (int mt = 0; mt < 4; mt++) {
        #pragma unroll
        for (int nt = 0; nt < 4; nt++) {
            int row0 = m0 + wm * 64 + mt * 16 + g;
            int col0 = n0 + wn * 32 + nt * 8 + t4 * 2;
            #pragma unroll
            for (int r = 0; r < 4; r++) {
                int row = row0 + (r >> 1) * 8;
                int col = col0 + (r & 1);
                float y = acc[mt][nt][r] + bias[col];
                int b_  = row >> 10;
                int s   = row & 1023;
                int h   = col >> 6;
                int hd  = col & 63;
                size_t idx = (((size_t)(b_ * HH + h) * SS) + s) * HD + hd;
                if (z == 1) y = y * scale + rel[s * HD + hd];
                Y[idx] = y;
            }
        }
    }
}

// Output projection: Y[M,N] = X @ Wo + bo (plain store).
__global__ void __launch_bounds__(256, 2) gemm_out(
    const float* __restrict__ X, const float* __restrict__ W,
    const float* __restrict__ bias, float* __restrict__ Y)
{
    __shared__ GemmSmem sm;

    const int tid  = threadIdx.x;
    const int warp = tid >> 5;
    const int lane = tid & 31;
    const int g    = lane >> 2;
    const int t4   = lane & 3;
    const int wm   = warp & 1;
    const int wn   = warp >> 1;
    const int m0   = blockIdx.y * 128;
    const int n0   = blockIdx.x * 128;

    float acc[4][4][4];
    #pragma unroll
    for (int mt = 0; mt < 4; mt++)
        #pragma unroll
        for (int nt = 0; nt < 4; nt++)
            #pragma unroll
            for (int r = 0; r < 4; r++) acc[mt][nt][r] = 0.f;

    gemm_body(X, W, sm, acc, m0, n0);

    #pragma unroll
    for (int mt = 0; mt < 4; mt++) {
        #pragma unroll
        for (int nt = 0; nt < 4; nt++) {
            int row0 = m0 + wm * 64 + mt * 16 + g;
            int col0 = n0 + wn * 32 + nt * 8 + t4 * 2;
            #pragma unroll
            for (int r = 0; r < 4; r++) {
                int row = row0 + (r >> 1) * 8;
                int col = col0 + (r & 1);
                Y[(size_t)row * DD + col] = acc[mt][nt][r] + bias[col];
            }
        }
    }
}

// ---------------------------------------------------------------------------
// Flash attention with tf32 tensor cores (unchanged).
// ---------------------------------------------------------------------------
struct AttnSmem {
    union {
        unsigned q[128][68];
        struct {
            unsigned k[64][68];
            unsigned v[64][72];
        } kv;
    } u;
    float mbias[64];
};

__global__ void __launch_bounds__(256, 2) attn_mma(
    const float* __restrict__ Q, const float* __restrict__ Kp,
    const float* __restrict__ V, const int* __restrict__ mask,
    float* __restrict__ ctx)
{
    __shared__ AttnSmem sm;

    const int tid  = threadIdx.x;
    const int warp = tid >> 5;
    const int lane = tid & 31;
    const int g    = lane >> 2;
    const int t4   = lane & 3;
    const int bh   = blockIdx.y;
    const int b    = bh >> 4;
    const int h    = bh & 15;
    const int s0   = blockIdx.x << 7;

    const float* Qb = Q  + (size_t)bh * SS * HD;
    const float* Kb = Kp + (size_t)bh * SS * HD;
    const float* Vb = V  + (size_t)bh * SS * HD;
    const int*   mb = mask + b * SS;

    #pragma unroll
    for (int i = 0; i < 8; i++) {
        int idx = tid + i * 256;
        int row = idx >> 4;
        int c   = idx & 15;
        float4 v = *(const float4*)(Qb + (size_t)(s0 + row) * HD + c * 4);
        sm.u.q[row][c*4+0] = f2tf(v.x);
        sm.u.q[row][c*4+1] = f2tf(v.y);
        sm.u.q[row][c*4+2] = f2tf(v.z);
        sm.u.q[row][c*4+3] = f2tf(v.w);
    }
    __syncthreads();

    unsigned Qa[8][4];
    {
        const int mr = warp * 16;
        #pragma unroll
        for (int kt = 0; kt < 8; kt++) {
            Qa[kt][0] = sm.u.q[mr + g    ][kt*8 + t4];
            Qa[kt][1] = sm.u.q[mr + g + 8][kt*8 + t4];
            Qa[kt][2] = sm.u.q[mr + g    ][kt*8 + t4 + 4];
            Qa[kt][3] = sm.u.q[mr + g + 8][kt*8 + t4 + 4];
        }
    }
    __syncthreads();

    float Oc[8][4];
    #pragma unroll
    for (int nt = 0; nt < 8; nt++)
        #pragma unroll
        for (int r = 0; r < 4; r++) Oc[nt][r] = 0.f;
    float m0r = -1e30f, m1r = -1e30f, l0r = 0.f, l1r = 0.f;

    const int src0 = (lane & ~3) | (t4 >> 1);
    const int src2 = (lane & ~3) | ((t4 >> 1) + 2);
    const bool selodd = (t4 & 1);

    for (int t0 = 0; t0 < SS; t0 += 64) {
        #pragma unroll
        for (int i = 0; i < 4; i++) {
            int idx = tid + i * 256;
            int row = idx >> 4;
            int c   = idx & 15;
            float4 kv = *(const float4*)(Kb + (size_t)(t0 + row) * HD + c * 4);
            sm.u.kv.k[row][c*4+0] = f2tf(kv.x);
            sm.u.kv.k[row][c*4+1] = f2tf(kv.y);
            sm.u.kv.k[row][c*4+2] = f2tf(kv.z);
            sm.u.kv.k[row][c*4+3] = f2tf(kv.w);
            float4 vv = *(const float4*)(Vb + (size_t)(t0 + row) * HD + c * 4);
            sm.u.kv.v[row][c*4+0] = f2tf(vv.x);
            sm.u.kv.v[row][c*4+1] = f2tf(vv.y);
            sm.u.kv.v[row][c*4+2] = f2tf(vv.z);
            sm.u.kv.v[row][c*4+3] = f2tf(vv.w);
        }
        if (tid < 64) sm.mbias[tid] = (mb[t0 + tid] == 0) ? -1e30f : 0.f;
        __syncthreads();

        float s[8][4];
        #pragma unroll
        for (int nt = 0; nt < 8; nt++) {
            s[nt][0] = s[nt][1] = s[nt][2] = s[nt][3] = 0.f;
            #pragma unroll
            for (int kt = 0; kt < 8; kt++) {
                unsigned bf[2];
                bf[0] = sm.u.kv.k[nt*8 + g][kt*8 + t4];
                bf[1] = sm.u.kv.k[nt*8 + g][kt*8 + t4 + 4];
                mma_tf32(s[nt], Qa[kt], bf);
            }
            float mb0 = sm.mbias[nt*8 + 2*t4];
            float mb1 = sm.mbias[nt*8 + 2*t4 + 1];
            s[nt][0] += mb0; s[nt][1] += mb1;
            s[nt][2] += mb0; s[nt][3] += mb1;
        }

        float mx0 = -1e30f, mx1 = -1e30f;
        #pragma unroll
        for (int nt = 0; nt < 8; nt++) {
            mx0 = fmaxf(mx0, fmaxf(s[nt][0], s[nt][1]));
            mx1 = fmaxf(mx1, fmaxf(s[nt][2], s[nt][3]));
        }
        mx0 = fmaxf(mx0, __shfl_xor_sync(0xffffffffu, mx0, 1));
        mx0 = fmaxf(mx0, __shfl_xor_sync(0xffffffffu, mx0, 2));
        mx1 = fmaxf(mx1, __shfl_xor_sync(0xffffffffu, mx1, 1));
        mx1 = fmaxf(mx1, __shfl_xor_sync(0xffffffffu, mx1, 2));

        float nm0 = fmaxf(m0r, mx0);
        float nm1 = fmaxf(m1r, mx1);
        float al0 = __expf(m0r - nm0);
        float al1 = __expf(m1r - nm1);
        m0r = nm0; m1r = nm1;

        unsigned pu[8][4];
        float rs0 = 0.f, rs1 = 0.f;
        #pragma unroll
        for (int nt = 0; nt < 8; nt++) {
            float p0 = __expf(s[nt][0] - nm0);
            float p1 = __expf(s[nt][1] - nm0);
            float p2 = __expf(s[nt][2] - nm1);
            float p3 = __expf(s[nt][3] - nm1);
            rs0 += p0 + p1;
            rs1 += p2 + p3;
            pu[nt][0] = f2tf(p0);
            pu[nt][1] = f2tf(p1);
            pu[nt][2] = f2tf(p2);
            pu[nt][3] = f2tf(p3);
        }
        rs0 += __shfl_xor_sync(0xffffffffu, rs0, 1);
        rs0 += __shfl_xor_sync(0xffffffffu, rs0, 2);
        rs1 += __shfl_xor_sync(0xffffffffu, rs1, 1);
        rs1 += __shfl_xor_sync(0xffffffffu, rs1, 2);
        l0r = l0r * al0 + rs0;
        l1r = l1r * al1 + rs1;

        #pragma unroll
        for (int nt = 0; nt < 8; nt++) {
            Oc[nt][0] *= al0; Oc[nt][1] *= al0;
            Oc[nt][2] *= al1; Oc[nt][3] *= al1;
        }

        #pragma unroll
        for (int kt = 0; kt < 8; kt++) {
            unsigned aP[4];
            unsigned v00 = __shfl_sync(0xffffffffu, pu[kt][0], src0);
            unsigned v01 = __shfl_sync(0xffffffffu, pu[kt][1], src0);
            unsigned v20 = __shfl_sync(0xffffffffu, pu[kt][2], src0);
            unsigned v21 = __shfl_sync(0xffffffffu, pu[kt][3], src0);
            unsigned w00 = __shfl_sync(0xffffffffu, pu[kt][0], src2);
            unsigned w01 = __shfl_sync(0xffffffffu, pu[kt][1], src2);
            unsigned w20 = __shfl_sync(0xffffffffu, pu[kt][2], src2);
            unsigned w21 = __shfl_sync(0xffffffffu, pu[kt][3], src2);
            aP[0] = selodd ? v01 : v00;
            aP[1] = selodd ? v21 : v20;
            aP[2] = selodd ? w01 : w00;
            aP[3] = selodd ? w21 : w20;
            #pragma unroll
            for (int nt = 0; nt < 8; nt++) {
                unsigned bf[2];
                bf[0] = sm.u.kv.v[kt*8 + t4    ][nt*8 + g];
                bf[1] = sm.u.kv.v[kt*8 + t4 + 4][nt*8 + g];
                mma_tf32(Oc[nt], aP, bf);
            }
        }
        __syncthreads();
    }

    const float inv0 = 1.0f / l0r;
    const float inv1 = 1.0f / l1r;
    const int r0 = s0 + warp * 16 + g;
    #pragma unroll
    for (int nt = 0; nt < 8; nt++) {
        int col = h * 64 + nt * 8 + 2 * t4;
        float2 o0 = make_float2(Oc[nt][0] * inv0, Oc[nt][1] * inv0);
        float2 o1 = make_float2(Oc[nt][2] * inv1, Oc[nt][3] * inv1);
        *(float2*)(ctx + ((size_t)b * SS + r0    ) * DD + col) = o0;
        *(float2*)(ctx + ((size_t)b * SS + r0 + 8) * DD + col) = o1;
    }
}

// ---------------------------------------------------------------------------

extern "C" void kernel_launch(void* const* d_in, const int* in_sizes, int n_in,
                              void* d_out, int out_size) {
    const float* x    = (const float*)d_in[0];
    const float* rel  = (const float*)d_in[1];
    const int*   mask = (const int*)  d_in[2];
    const float* Wq   = (const float*)d_in[3];
    const float* bq   = (const float*)d_in[4];
    const float* Wk   = (const float*)d_in[5];
    const float* bk   = (const float*)d_in[6];
    const float* Wv   = (const float*)d_in[7];
    const float* bv   = (const float*)d_in[8];
    const float* Wo   = (const float*)d_in[9];
    const float* bo   = (const float*)d_in[10];
    float* out = (float*)d_out;

    float *dQ, *dK, *dV, *dCtx;
    cudaGetSymbolAddress((void**)&dQ,   g_Q);
    cudaGetSymbolAddress((void**)&dK,   g_K);
    cudaGetSymbolAddress((void**)&dV,   g_V);
    cudaGetSymbolAddress((void**)&dCtx, g_ctx);

    gemm_qkv<<<dim3(DD / 128, MROWS / 128, 3), 256>>>(
        x, Wq, Wk, Wv, bq, bk, bv, rel, dQ, dK, dV);

    attn_mma<<<dim3(SS / 128, BB * HH), 256>>>(dQ, dK, dV, mask, dCtx);

    gemm_out<<<dim3(DD / 128, MROWS / 128), 256>>>(dCtx, Wo, bo, out);
}

// round 16
// speedup vs baseline: 2.1539x; 2.1539x over previous
#include <cuda_runtime.h>
#include <cuda_fp16.h>
#include <cuda_bf16.h>

// Problem constants
#define BB 8
#define SS 1024
#define DD 1024
#define HH 16
#define HD 64
#define MROWS (BB*SS)     // 8192

#define NSTAGE 4
#define STAGE_BYTES 18944          // Xs 128x40 halves (10240B) + Ws 32x136 halves (8704B)
#define WS_OFF 10240

// Scratch (device globals; no allocation allowed)
__device__ float  g_Q[(size_t)BB*HH*SS*HD];
__device__ float  g_K[(size_t)BB*HH*SS*HD];
__device__ float  g_V[(size_t)BB*HH*SS*HD];
__device__ __half g_xh[(size_t)MROWS*DD];
__device__ __half g_wh[4][(size_t)DD*DD];
__device__ __half g_ctxh[(size_t)MROWS*DD];

__device__ __forceinline__ unsigned f2tf(float f) {
    unsigned u;
    asm("cvt.rna.tf32.f32 %0, %1;" : "=r"(u) : "f"(f));
    return u;
}

__device__ __forceinline__ unsigned pack_h2(float lo, float hi) {
    unsigned u;
    asm("cvt.rn.f16x2.f32 %0, %1, %2;" : "=r"(u) : "f"(hi), "f"(lo));
    return u;
}

__device__ __forceinline__ void mma_tf32(float c[4], const unsigned a[4], const unsigned b[2]) {
    asm volatile(
        "mma.sync.aligned.m16n8k8.row.col.f32.tf32.tf32.f32 "
        "{%0,%1,%2,%3}, {%4,%5,%6,%7}, {%8,%9}, {%0,%1,%2,%3};"
        : "+f"(c[0]), "+f"(c[1]), "+f"(c[2]), "+f"(c[3])
        : "r"(a[0]), "r"(a[1]), "r"(a[2]), "r"(a[3]),
          "r"(b[0]), "r"(b[1]));
}

__device__ __forceinline__ void mma_f16(float c[4], const unsigned a[4], const unsigned b[2]) {
    asm volatile(
        "mma.sync.aligned.m16n8k16.row.col.f32.f16.f16.f32 "
        "{%0,%1,%2,%3}, {%4,%5,%6,%7}, {%8,%9}, {%0,%1,%2,%3};"
        : "+f"(c[0]), "+f"(c[1]), "+f"(c[2]), "+f"(c[3])
        : "r"(a[0]), "r"(a[1]), "r"(a[2]), "r"(a[3]),
          "r"(b[0]), "r"(b[1]));
}

__device__ __forceinline__ void ldsm_x4(unsigned r[4], unsigned addr) {
    asm volatile(
        "ldmatrix.sync.aligned.m8n8.x4.shared.b16 {%0,%1,%2,%3}, [%4];"
        : "=r"(r[0]), "=r"(r[1]), "=r"(r[2]), "=r"(r[3]) : "r"(addr));
}

__device__ __forceinline__ void ldsm_x4_trans(unsigned r[4], unsigned addr) {
    asm volatile(
        "ldmatrix.sync.aligned.m8n8.x4.trans.shared.b16 {%0,%1,%2,%3}, [%4];"
        : "=r"(r[0]), "=r"(r[1]), "=r"(r[2]), "=r"(r[3]) : "r"(addr));
}

__device__ __forceinline__ void cpa16(unsigned dst, const __half* src) {
    asm volatile("cp.async.cg.shared.global [%0], [%1], 16;" :: "r"(dst), "l"(src));
}
__device__ __forceinline__ void cpa_commit() {
    asm volatile("cp.async.commit_group;");
}

// ---------------------------------------------------------------------------
// fp32 -> fp16 conversion kernels
// ---------------------------------------------------------------------------
__global__ void f2h_x(const float4* __restrict__ src, __half* __restrict__ dst) {
    int i = blockIdx.x * blockDim.x + threadIdx.x;     // covers MROWS*DD/4
    float4 v = src[i];
    __half2* d = (__half2*)(dst + (size_t)i * 4);
    d[0] = __floats2half2_rn(v.x, v.y);
    d[1] = __floats2half2_rn(v.z, v.w);
}

__global__ void f2h_w(const float4* __restrict__ w0, const float4* __restrict__ w1,
                      const float4* __restrict__ w2, const float4* __restrict__ w3,
                      __half* __restrict__ dst) {
    int i = blockIdx.x * blockDim.x + threadIdx.x;     // covers DD*DD/4
    int z = blockIdx.y;
    const float4* s = (z == 0) ? w0 : (z == 1) ? w1 : (z == 2) ? w2 : w3;
    float4 v = s[i];
    __half2* d = (__half2*)(dst + (size_t)z * DD * DD + (size_t)i * 4);
    d[0] = __floats2half2_rn(v.x, v.y);
    d[1] = __floats2half2_rn(v.z, v.w);
}

// ---------------------------------------------------------------------------
// cp.async 4-stage pipelined fp16 GEMM body.
// Tile BM=BN=128, BK=32; 256 threads = 8 warps (warp 64x32).
// Stage layout: Xs [128][40] halves @0, Ws [32][136] halves @WS_OFF.
// Per k-tile: wait_group(2) -> barrier -> MMA(stage kt%4) -> issue(kt+3) -> commit.
// ---------------------------------------------------------------------------
__device__ __forceinline__ void g_issue(
    const __half* __restrict__ Xh, const __half* __restrict__ Wh,
    unsigned sbase, int m0, int n0, int kt,
    int xr, int xc, int wr, int wc)
{
    const int k0 = kt * 32;
    unsigned xd = sbase + (unsigned)(xr * 80 + xc * 2);
    const __half* xs = Xh + (size_t)(m0 + xr) * DD + k0 + xc;
    cpa16(xd, xs);
    cpa16(xd + 16, xs + 8);
    unsigned wd = sbase + WS_OFF + (unsigned)(wr * 272 + wc * 2);
    const __half* ws = Wh + (size_t)(k0 + wr) * DD + n0 + wc;
    cpa16(wd, ws);
    cpa16(wd + 16, ws + 8);
}

__device__ __forceinline__ void g_mma_st(
    unsigned sbase, const unsigned aOff[4], unsigned bOff, float acc[4][4][4])
{
    #pragma unroll
    for (int ks = 0; ks < 2; ks++) {
        unsigned a[4][4], b[4][2];
        #pragma unroll
        for (int mt = 0; mt < 4; mt++)
            ldsm_x4(a[mt], sbase + aOff[mt] + (unsigned)(ks * 32));
        {
            unsigned r[4];
            ldsm_x4_trans(r, sbase + bOff + (unsigned)(ks * 16 * 272));
            b[0][0] = r[0]; b[0][1] = r[1];
            b[1][0] = r[2]; b[1][1] = r[3];
            ldsm_x4_trans(r, sbase + bOff + (unsigned)(ks * 16 * 272 + 32));
            b[2][0] = r[0]; b[2][1] = r[1];
            b[3][0] = r[2]; b[3][1] = r[3];
        }
        #pragma unroll
        for (int mt = 0; mt < 4; mt++)
            #pragma unroll
            for (int nt = 0; nt < 4; nt++)
                mma_f16(acc[mt][nt], a[mt], b[nt]);
    }
}

__device__ __forceinline__ void gemm_body(
    const __half* __restrict__ Xh, const __half* __restrict__ Wh,
    char* smem, float acc[4][4][4], int m0, int n0)
{
    const int tid  = threadIdx.x;
    const int lane = tid & 31;
    const int warp = tid >> 5;
    const int wm   = warp & 1;
    const int wn   = warp >> 1;

    const int xr = tid >> 1, xc = (tid & 1) * 16;
    const int wr = tid >> 3, wc = (tid & 7) * 16;

    const unsigned s0 = (unsigned)__cvta_generic_to_shared(smem);
    unsigned aOff[4];
    #pragma unroll
    for (int mt = 0; mt < 4; mt++) {
        int row = wm * 64 + mt * 16 + (lane & 15);
        aOff[mt] = (unsigned)(row * 80 + (lane >> 4) * 16);
    }
    const unsigned bOff = WS_OFF
        + (unsigned)(((lane & 7) + ((lane >> 3) & 1) * 8) * 272
                     + (wn * 32 + (lane >> 4) * 8) * 2);

    // prologue: stages 0..2
    #pragma unroll
    for (int p = 0; p < 3; p++) {
        g_issue(Xh, Wh, s0 + p * STAGE_BYTES, m0, n0, p, xr, xc, wr, wc);
        cpa_commit();
    }

    #pragma unroll 1
    for (int kt = 0; kt < 32; kt++) {
        asm volatile("cp.async.wait_group 2;");
        __syncthreads();
        g_mma_st(s0 + (unsigned)((kt & 3) * STAGE_BYTES), aOff, bOff, acc);
        if (kt + 3 < 32)
            g_issue(Xh, Wh, s0 + (unsigned)(((kt + 3) & 3) * STAGE_BYTES),
                    m0, n0, kt + 3, xr, xc, wr, wc);
        cpa_commit();   // always commit (empty groups keep wait_group(2) exact)
    }
}

// Fused Q/K/V projection: z = blockIdx.z selects weights/bias/epilogue.
__global__ void __launch_bounds__(256, 2) gemm_qkv(
    const __half* __restrict__ Xh, const __half* __restrict__ Whall,
    const float* __restrict__ bq, const float* __restrict__ bk, const float* __restrict__ bv,
    const float* __restrict__ rel,
    float* __restrict__ Qo, float* __restrict__ Ko, float* __restrict__ Vo)
{
    extern __shared__ __align__(16) char smem[];

    const int z = blockIdx.z;
    const __half* Wh   = Whall + (size_t)z * DD * DD;
    const float*  bias = (z == 0) ? bq : (z == 1) ? bk : bv;
    float*        Y    = (z == 0) ? Qo : (z == 1) ? Ko : Vo;

    const int tid  = threadIdx.x;
    const int warp = tid >> 5;
    const int lane = tid & 31;
    const int g    = lane >> 2;
    const int t4   = lane & 3;
    const int wm   = warp & 1;
    const int wn   = warp >> 1;
    const int m0   = blockIdx.y * 128;
    const int n0   = blockIdx.x * 128;

    float acc[4][4][4];
    #pragma unroll
    for (int mt = 0; mt < 4; mt++)
        #pragma unroll
        for (int nt = 0; nt < 4; nt++)
            #pragma unroll
            for (int r = 0; r < 4; r++) acc[mt][nt][r] = 0.f;

    gemm_body(Xh, Wh, smem, acc, m0, n0);

    const float scale = 0.125f;   // HD^-0.5
    #pragma unroll
    for (int mt = 0; mt < 4; mt++) {
        #pragma unroll
        for (int nt = 0; nt < 4; nt++) {
            int row0 = m0 + wm * 64 + mt * 16 + g;
            int col0 = n0 + wn * 32 + nt * 8 + t4 * 2;
            #pragma unroll
            for (int r = 0; r < 4; r++) {
                int row = row0 + (r >> 1) * 8;
                int col = col0 + (r & 1);
                float y = acc[mt][nt][r] + bias[col];
                int b_  = row >> 10;
                int s   = row & 1023;
                int h   = col >> 6;
                int hd  = col & 63;
                size_t idx = (((size_t)(b_ * HH + h) * SS) + s) * HD + hd;
                if (z == 1) y = y * scale + rel[s * HD + hd];
                Y[idx] = y;
            }
        }
    }
}

// Output projection: Y[M,N] = ctx(fp16) @ Wo + bo (fp32 store).
__global__ void __launch_bounds__(256, 2) gemm_out(
    const __half* __restrict__ Xh, const __half* __restrict__ Wh,
    const float* __restrict__ bias, float* __restrict__ Y)
{
    extern __shared__ __align__(16) char smem[];

    const int tid  = threadIdx.x;
    const int warp = tid >> 5;
    const int lane = tid & 31;
    const int g    = lane >> 2;
    const int t4   = lane & 3;
    const int wm   = warp & 1;
    const int wn   = warp >> 1;
    const int m0   = blockIdx.y * 128;
    const int n0   = blockIdx.x * 128;

    float acc[4][4][4];
    #pragma unroll
    for (int mt = 0; mt < 4; mt++)
        #pragma unroll
        for (int nt = 0; nt < 4; nt++)
            #pragma unroll
            for (int r = 0; r < 4; r++) acc[mt][nt][r] = 0.f;

    gemm_body(Xh, Wh, smem, acc, m0, n0);

    #pragma unroll
    for (int mt = 0; mt < 4; mt++) {
        #pragma unroll
        for (int nt = 0; nt < 4; nt++) {
            int row0 = m0 + wm * 64 + mt * 16 + g;
            int col0 = n0 + wn * 32 + nt * 8 + t4 * 2;
            #pragma unroll
            for (int r = 0; r < 4; r++) {
                int row = row0 + (r >> 1) * 8;
                int col = col0 + (r & 1);
                Y[(size_t)row * DD + col] = acc[mt][nt][r] + bias[col];
            }
        }
    }
}

// ---------------------------------------------------------------------------
// Flash attention with tf32 tensor cores (unchanged except fp16 ctx output).
// ---------------------------------------------------------------------------
struct AttnSmem {
    union {
        unsigned q[128][68];
        struct {
            unsigned k[64][68];
            unsigned v[64][72];
        } kv;
    } u;
    float mbias[64];
};

__global__ void __launch_bounds__(256, 2) attn_mma(
    const float* __restrict__ Q, const float* __restrict__ Kp,
    const float* __restrict__ V, const int* __restrict__ mask,
    __half* __restrict__ ctx)
{
    __shared__ AttnSmem sm;

    const int tid  = threadIdx.x;
    const int warp = tid >> 5;
    const int lane = tid & 31;
    const int g    = lane >> 2;
    const int t4   = lane & 3;
    const int bh   = blockIdx.y;
    const int b    = bh >> 4;
    const int h    = bh & 15;
    const int s0   = blockIdx.x << 7;

    const float* Qb = Q  + (size_t)bh * SS * HD;
    const float* Kb = Kp + (size_t)bh * SS * HD;
    const float* Vb = V  + (size_t)bh * SS * HD;
    const int*   mb = mask + b * SS;

    #pragma unroll
    for (int i = 0; i < 8; i++) {
        int idx = tid + i * 256;
        int row = idx >> 4;
        int c   = idx & 15;
        float4 v = *(const float4*)(Qb + (size_t)(s0 + row) * HD + c * 4);
        sm.u.q[row][c*4+0] = f2tf(v.x);
        sm.u.q[row][c*4+1] = f2tf(v.y);
        sm.u.q[row][c*4+2] = f2tf(v.z);
        sm.u.q[row][c*4+3] = f2tf(v.w);
    }
    __syncthreads();

    unsigned Qa[8][4];
    {
        const int mr = warp * 16;
        #pragma unroll
        for (int kt = 0; kt < 8; kt++) {
            Qa[kt][0] = sm.u.q[mr + g    ][kt*8 + t4];
            Qa[kt][1] = sm.u.q[mr + g + 8][kt*8 + t4];
            Qa[kt][2] = sm.u.q[mr + g    ][kt*8 + t4 + 4];
            Qa[kt][3] = sm.u.q[mr + g + 8][kt*8 + t4 + 4];
        }
    }
    __syncthreads();

    float Oc[8][4];
    #pragma unroll
    for (int nt = 0; nt < 8; nt++)
        #pragma unroll
        for (int r = 0; r < 4; r++) Oc[nt][r] = 0.f;
    float m0r = -1e30f, m1r = -1e30f, l0r = 0.f, l1r = 0.f;

    const int src0 = (lane & ~3) | (t4 >> 1);
    const int src2 = (lane & ~3) | ((t4 >> 1) + 2);
    const bool selodd = (t4 & 1);

    for (int t0 = 0; t0 < SS; t0 += 64) {
        #pragma unroll
        for (int i = 0; i < 4; i++) {
            int idx = tid + i * 256;
            int row = idx >> 4;
            int c   = idx & 15;
            float4 kv = *(const float4*)(Kb + (size_t)(t0 + row) * HD + c * 4);
            sm.u.kv.k[row][c*4+0] = f2tf(kv.x);
            sm.u.kv.k[row][c*4+1] = f2tf(kv.y);
            sm.u.kv.k[row][c*4+2] = f2tf(kv.z);
            sm.u.kv.k[row][c*4+3] = f2tf(kv.w);
            float4 vv = *(const float4*)(Vb + (size_t)(t0 + row) * HD + c * 4);
            sm.u.kv.v[row][c*4+0] = f2tf(vv.x);
            sm.u.kv.v[row][c*4+1] = f2tf(vv.y);
            sm.u.kv.v[row][c*4+2] = f2tf(vv.z);
            sm.u.kv.v[row][c*4+3] = f2tf(vv.w);
        }
        if (tid < 64) sm.mbias[tid] = (mb[t0 + tid] == 0) ? -1e30f : 0.f;
        __syncthreads();

        float s[8][4];
        #pragma unroll
        for (int nt = 0; nt < 8; nt++) {
            s[nt][0] = s[nt][1] = s[nt][2] = s[nt][3] = 0.f;
            #pragma unroll
            for (int kt = 0; kt < 8; kt++) {
                unsigned bf[2];
                bf[0] = sm.u.kv.k[nt*8 + g][kt*8 + t4];
                bf[1] = sm.u.kv.k[nt*8 + g][kt*8 + t4 + 4];
                mma_tf32(s[nt], Qa[kt], bf);
            }
            float mb0 = sm.mbias[nt*8 + 2*t4];
            float mb1 = sm.mbias[nt*8 + 2*t4 + 1];
            s[nt][0] += mb0; s[nt][1] += mb1;
            s[nt][2] += mb0; s[nt][3] += mb1;
        }

        float mx0 = -1e30f, mx1 = -1e30f;
        #pragma unroll
        for (int nt = 0; nt < 8; nt++) {
            mx0 = fmaxf(mx0, fmaxf(s[nt][0], s[nt][1]));
            mx1 = fmaxf(mx1, fmaxf(s[nt][2], s[nt][3]));
        }
        mx0 = fmaxf(mx0, __shfl_xor_sync(0xffffffffu, mx0, 1));
        mx0 = fmaxf(mx0, __shfl_xor_sync(0xffffffffu, mx0, 2));
        mx1 = fmaxf(mx1, __shfl_xor_sync(0xffffffffu, mx1, 1));
        mx1 = fmaxf(mx1, __shfl_xor_sync(0xffffffffu, mx1, 2));

        float nm0 = fmaxf(m0r, mx0);
        float nm1 = fmaxf(m1r, mx1);
        float al0 = __expf(m0r - nm0);
        float al1 = __expf(m1r - nm1);
        m0r = nm0; m1r = nm1;

        unsigned pu[8][4];
        float rs0 = 0.f, rs1 = 0.f;
        #pragma unroll
        for (int nt = 0; nt < 8; nt++) {
            float p0 = __expf(s[nt][0] - nm0);
            float p1 = __expf(s[nt][1] - nm0);
            float p2 = __expf(s[nt][2] - nm1);
            float p3 = __expf(s[nt][3] - nm1);
            rs0 += p0 + p1;
            rs1 += p2 + p3;
            pu[nt][0] = f2tf(p0);
            pu[nt][1] = f2tf(p1);
            pu[nt][2] = f2tf(p2);
            pu[nt][3] = f2tf(p3);
        }
        rs0 += __shfl_xor_sync(0xffffffffu, rs0, 1);
        rs0 += __shfl_xor_sync(0xffffffffu, rs0, 2);
        rs1 += __shfl_xor_sync(0xffffffffu, rs1, 1);
        rs1 += __shfl_xor_sync(0xffffffffu, rs1, 2);
        l0r = l0r * al0 + rs0;
        l1r = l1r * al1 + rs1;

        #pragma unroll
        for (int nt = 0; nt < 8; nt++) {
            Oc[nt][0] *= al0; Oc[nt][1] *= al0;
            Oc[nt][2] *= al1; Oc[nt][3] *= al1;
        }

        #pragma unroll
        for (int kt = 0; kt < 8; kt++) {
            unsigned aP[4];
            unsigned v00 = __shfl_sync(0xffffffffu, pu[kt][0], src0);
            unsigned v01 = __shfl_sync(0xffffffffu, pu[kt][1], src0);
            unsigned v20 = __shfl_sync(0xffffffffu, pu[kt][2], src0);
            unsigned v21 = __shfl_sync(0xffffffffu, pu[kt][3], src0);
            unsigned w00 = __shfl_sync(0xffffffffu, pu[kt][0], src2);
            unsigned w01 = __shfl_sync(0xffffffffu, pu[kt][1], src2);
            unsigned w20 = __shfl_sync(0xffffffffu, pu[kt][2], src2);
            unsigned w21 = __shfl_sync(0xffffffffu, pu[kt][3], src2);
            aP[0] = selodd ? v01 : v00;
            aP[1] = selodd ? v21 : v20;
            aP[2] = selodd ? w01 : w00;
            aP[3] = selodd ? w21 : w20;
            #pragma unroll
            for (int nt = 0; nt < 8; nt++) {
                unsigned bf[2];
                bf[0] = sm.u.kv.v[kt*8 + t4    ][nt*8 + g];
                bf[1] = sm.u.kv.v[kt*8 + t4 + 4][nt*8 + g];
                mma_tf32(Oc[nt], aP, bf);
            }
        }
        __syncthreads();
    }

    const float inv0 = 1.0f / l0r;
    const float inv1 = 1.0f / l1r;
    const int r0 = s0 + warp * 16 + g;
    #pragma unroll
    for (int nt = 0; nt < 8; nt++) {
        int col = h * 64 + nt * 8 + 2 * t4;
        unsigned o0 = pack_h2(Oc[nt][0] * inv0, Oc[nt][1] * inv0);
        unsigned o1 = pack_h2(Oc[nt][2] * inv1, Oc[nt][3] * inv1);
        *(unsigned*)(ctx + ((size_t)b * SS + r0    ) * DD + col) = o0;
        *(unsigned*)(ctx + ((size_t)b * SS + r0 + 8) * DD + col) = o1;
    }
}

// ---------------------------------------------------------------------------

extern "C" void kernel_launch(void* const* d_in, const int* in_sizes, int n_in,
                              void* d_out, int out_size) {
    const float* x    = (const float*)d_in[0];
    const float* rel  = (const float*)d_in[1];
    const int*   mask = (const int*)  d_in[2];
    const float* Wq   = (const float*)d_in[3];
    const float* bq   = (const float*)d_in[4];
    const float* Wk   = (const float*)d_in[5];
    const float* bk   = (const float*)d_in[6];
    const float* Wv   = (const float*)d_in[7];
    const float* bv   = (const float*)d_in[8];
    const float* Wo   = (const float*)d_in[9];
    const float* bo   = (const float*)d_in[10];
    float* out = (float*)d_out;

    float *dQ, *dK, *dV;
    __half *dXh, *dWh, *dCtxh;
    cudaGetSymbolAddress((void**)&dQ,    g_Q);
    cudaGetSymbolAddress((void**)&dK,    g_K);
    cudaGetSymbolAddress((void**)&dV,    g_V);
    cudaGetSymbolAddress((void**)&dXh,   g_xh);
    cudaGetSymbolAddress((void**)&dWh,   g_wh);
    cudaGetSymbolAddress((void**)&dCtxh, g_ctxh);

    cudaFuncSetAttribute(gemm_qkv, cudaFuncAttributeMaxDynamicSharedMemorySize,
                         NSTAGE * STAGE_BYTES);
    cudaFuncSetAttribute(gemm_out, cudaFuncAttributeMaxDynamicSharedMemorySize,
                         NSTAGE * STAGE_BYTES);

    // fp32 -> fp16 conversions
    f2h_x<<<(MROWS * DD / 4) / 256, 256>>>((const float4*)x, dXh);
    f2h_w<<<dim3((DD * DD / 4) / 256, 4), 256>>>(
        (const float4*)Wq, (const float4*)Wk, (const float4*)Wv, (const float4*)Wo, dWh);

    gemm_qkv<<<dim3(DD / 128, MROWS / 128, 3), 256, NSTAGE * STAGE_BYTES>>>(
        dXh, dWh, bq, bk, bv, rel, dQ, dK, dV);

    attn_mma<<<dim3(SS / 128, BB * HH), 256>>>(dQ, dK, dV, mask, dCtxh);

    gemm_out<<<dim3(DD / 128, MROWS / 128), 256, NSTAGE * STAGE_BYTES>>>(
        dCtxh, dWh + (size_t)3 * DD * DD, bo, out);
}

// round 17
// speedup vs baseline: 2.9867x; 1.3867x over previous
#include <cuda_runtime.h>
#include <cuda_fp16.h>
#include <cuda_bf16.h>

// Problem constants
#define BB 8
#define SS 1024
#define DD 1024
#define HH 16
#define HD 64
#define MROWS (BB*SS)     // 8192

#define NSTAGE 4
#define STAGE_BYTES 18944          // Xs 128x40 halves (10240B) + Ws 32x136 halves (8704B)
#define WS_OFF 10240

// Scratch (device globals; no allocation allowed)
__device__ __half g_Qh[(size_t)BB*HH*SS*HD];
__device__ __half g_Kh[(size_t)BB*HH*SS*HD];
__device__ __half g_Vh[(size_t)BB*HH*SS*HD];
__device__ __half g_xh[(size_t)MROWS*DD];
__device__ __half g_wh[4][(size_t)DD*DD];
__device__ __half g_ctxh[(size_t)MROWS*DD];

__device__ __forceinline__ unsigned pack_h2(float lo, float hi) {
    unsigned u;
    asm("cvt.rn.f16x2.f32 %0, %1, %2;" : "=r"(u) : "f"(hi), "f"(lo));
    return u;
}

__device__ __forceinline__ void mma_f16(float c[4], const unsigned a[4], const unsigned b[2]) {
    asm volatile(
        "mma.sync.aligned.m16n8k16.row.col.f32.f16.f16.f32 "
        "{%0,%1,%2,%3}, {%4,%5,%6,%7}, {%8,%9}, {%0,%1,%2,%3};"
        : "+f"(c[0]), "+f"(c[1]), "+f"(c[2]), "+f"(c[3])
        : "r"(a[0]), "r"(a[1]), "r"(a[2]), "r"(a[3]),
          "r"(b[0]), "r"(b[1]));
}

__device__ __forceinline__ void ldsm_x4(unsigned r[4], unsigned addr) {
    asm volatile(
        "ldmatrix.sync.aligned.m8n8.x4.shared.b16 {%0,%1,%2,%3}, [%4];"
        : "=r"(r[0]), "=r"(r[1]), "=r"(r[2]), "=r"(r[3]) : "r"(addr));
}

__device__ __forceinline__ void ldsm_x4_trans(unsigned r[4], unsigned addr) {
    asm volatile(
        "ldmatrix.sync.aligned.m8n8.x4.trans.shared.b16 {%0,%1,%2,%3}, [%4];"
        : "=r"(r[0]), "=r"(r[1]), "=r"(r[2]), "=r"(r[3]) : "r"(addr));
}

__device__ __forceinline__ void cpa16(unsigned dst, const __half* src) {
    asm volatile("cp.async.cg.shared.global [%0], [%1], 16;" :: "r"(dst), "l"(src));
}
__device__ __forceinline__ void cpa_commit() {
    asm volatile("cp.async.commit_group;");
}

// ---------------------------------------------------------------------------
// fp32 -> fp16 conversion kernels
// ---------------------------------------------------------------------------
__global__ void f2h_x(const float4* __restrict__ src, __half* __restrict__ dst) {
    int i = blockIdx.x * blockDim.x + threadIdx.x;
    float4 v = src[i];
    __half2* d = (__half2*)(dst + (size_t)i * 4);
    d[0] = __floats2half2_rn(v.x, v.y);
    d[1] = __floats2half2_rn(v.z, v.w);
}

__global__ void f2h_w(const float4* __restrict__ w0, const float4* __restrict__ w1,
                      const float4* __restrict__ w2, const float4* __restrict__ w3,
                      __half* __restrict__ dst) {
    int i = blockIdx.x * blockDim.x + threadIdx.x;
    int z = blockIdx.y;
    const float4* s = (z == 0) ? w0 : (z == 1) ? w1 : (z == 2) ? w2 : w3;
    float4 v = s[i];
    __half2* d = (__half2*)(dst + (size_t)z * DD * DD + (size_t)i * 4);
    d[0] = __floats2half2_rn(v.x, v.y);
    d[1] = __floats2half2_rn(v.z, v.w);
}

// ---------------------------------------------------------------------------
// cp.async 4-stage pipelined fp16 GEMM body (unchanged from R15).
// ---------------------------------------------------------------------------
__device__ __forceinline__ void g_issue(
    const __half* __restrict__ Xh, const __half* __restrict__ Wh,
    unsigned sbase, int m0, int n0, int kt,
    int xr, int xc, int wr, int wc)
{
    const int k0 = kt * 32;
    unsigned xd = sbase + (unsigned)(xr * 80 + xc * 2);
    const __half* xs = Xh + (size_t)(m0 + xr) * DD + k0 + xc;
    cpa16(xd, xs);
    cpa16(xd + 16, xs + 8);
    unsigned wd = sbase + WS_OFF + (unsigned)(wr * 272 + wc * 2);
    const __half* ws = Wh + (size_t)(k0 + wr) * DD + n0 + wc;
    cpa16(wd, ws);
    cpa16(wd + 16, ws + 8);
}

__device__ __forceinline__ void g_mma_st(
    unsigned sbase, const unsigned aOff[4], unsigned bOff, float acc[4][4][4])
{
    #pragma unroll
    for (int ks = 0; ks < 2; ks++) {
        unsigned a[4][4], b[4][2];
        #pragma unroll
        for (int mt = 0; mt < 4; mt++)
            ldsm_x4(a[mt], sbase + aOff[mt] + (unsigned)(ks * 32));
        {
            unsigned r[4];
            ldsm_x4_trans(r, sbase + bOff + (unsigned)(ks * 16 * 272));
            b[0][0] = r[0]; b[0][1] = r[1];
            b[1][0] = r[2]; b[1][1] = r[3];
            ldsm_x4_trans(r, sbase + bOff + (unsigned)(ks * 16 * 272 + 32));
            b[2][0] = r[0]; b[2][1] = r[1];
            b[3][0] = r[2]; b[3][1] = r[3];
        }
        #pragma unroll
        for (int mt = 0; mt < 4; mt++)
            #pragma unroll
            for (int nt = 0; nt < 4; nt++)
                mma_f16(acc[mt][nt], a[mt], b[nt]);
    }
}

__device__ __forceinline__ void gemm_body(
    const __half* __restrict__ Xh, const __half* __restrict__ Wh,
    char* smem, float acc[4][4][4], int m0, int n0)
{
    const int tid  = threadIdx.x;
    const int lane = tid & 31;
    const int warp = tid >> 5;
    const int wm   = warp & 1;
    const int wn   = warp >> 1;

    const int xr = tid >> 1, xc = (tid & 1) * 16;
    const int wr = tid >> 3, wc = (tid & 7) * 16;

    const unsigned s0 = (unsigned)__cvta_generic_to_shared(smem);
    unsigned aOff[4];
    #pragma unroll
    for (int mt = 0; mt < 4; mt++) {
        int row = wm * 64 + mt * 16 + (lane & 15);
        aOff[mt] = (unsigned)(row * 80 + (lane >> 4) * 16);
    }
    const unsigned bOff = WS_OFF
        + (unsigned)(((lane & 7) + ((lane >> 3) & 1) * 8) * 272
                     + (wn * 32 + (lane >> 4) * 8) * 2);

    #pragma unroll
    for (int p = 0; p < 3; p++) {
        g_issue(Xh, Wh, s0 + p * STAGE_BYTES, m0, n0, p, xr, xc, wr, wc);
        cpa_commit();
    }

    #pragma unroll 1
    for (int kt = 0; kt < 32; kt++) {
        asm volatile("cp.async.wait_group 2;");
        __syncthreads();
        g_mma_st(s0 + (unsigned)((kt & 3) * STAGE_BYTES), aOff, bOff, acc);
        if (kt + 3 < 32)
            g_issue(Xh, Wh, s0 + (unsigned)(((kt + 3) & 3) * STAGE_BYTES),
                    m0, n0, kt + 3, xr, xc, wr, wc);
        cpa_commit();
    }
}

// Fused Q/K/V projection -> fp16 outputs in [B,H,S,HD].
__global__ void __launch_bounds__(256, 2) gemm_qkv(
    const __half* __restrict__ Xh, const __half* __restrict__ Whall,
    const float* __restrict__ bq, const float* __restrict__ bk, const float* __restrict__ bv,
    const float* __restrict__ rel,
    __half* __restrict__ Qo, __half* __restrict__ Ko, __half* __restrict__ Vo)
{
    extern __shared__ __align__(16) char smem[];

    const int z = blockIdx.z;
    const __half* Wh   = Whall + (size_t)z * DD * DD;
    const float*  bias = (z == 0) ? bq : (z == 1) ? bk : bv;
    __half*       Y    = (z == 0) ? Qo : (z == 1) ? Ko : Vo;

    const int tid  = threadIdx.x;
    const int warp = tid >> 5;
    const int lane = tid & 31;
    const int g    = lane >> 2;
    const int t4   = lane & 3;
    const int wm   = warp & 1;
    const int wn   = warp >> 1;
    const int m0   = blockIdx.y * 128;
    const int n0   = blockIdx.x * 128;

    float acc[4][4][4];
    #pragma unroll
    for (int mt = 0; mt < 4; mt++)
        #pragma unroll
        for (int nt = 0; nt < 4; nt++)
            #pragma unroll
            for (int r = 0; r < 4; r++) acc[mt][nt][r] = 0.f;

    gemm_body(Xh, Wh, smem, acc, m0, n0);

    const float scale = 0.125f;   // HD^-0.5
    #pragma unroll
    for (int mt = 0; mt < 4; mt++) {
        #pragma unroll
        for (int nt = 0; nt < 4; nt++) {
            int row0 = m0 + wm * 64 + mt * 16 + g;
            int col0 = n0 + wn * 32 + nt * 8 + t4 * 2;
            #pragma unroll
            for (int rr = 0; rr < 2; rr++) {
                int row = row0 + rr * 8;
                float y0 = acc[mt][nt][rr * 2 + 0] + bias[col0];
                float y1 = acc[mt][nt][rr * 2 + 1] + bias[col0 + 1];
                int b_  = row >> 10;
                int s   = row & 1023;
                int h   = col0 >> 6;
                int hd  = col0 & 63;
                if (z == 1) {
                    y0 = y0 * scale + rel[s * HD + hd];
                    y1 = y1 * scale + rel[s * HD + hd + 1];
                }
                size_t idx = (((size_t)(b_ * HH + h) * SS) + s) * HD + hd;
                *(unsigned*)(Y + idx) = pack_h2(y0, y1);
            }
        }
    }
}

// Output projection: Y[M,N] = ctx(fp16) @ Wo + bo (fp32 store).
__global__ void __launch_bounds__(256, 2) gemm_out(
    const __half* __restrict__ Xh, const __half* __restrict__ Wh,
    const float* __restrict__ bias, float* __restrict__ Y)
{
    extern __shared__ __align__(16) char smem[];

    const int tid  = threadIdx.x;
    const int warp = tid >> 5;
    const int lane = tid & 31;
    const int g    = lane >> 2;
    const int t4   = lane & 3;
    const int wm   = warp & 1;
    const int wn   = warp >> 1;
    const int m0   = blockIdx.y * 128;
    const int n0   = blockIdx.x * 128;

    float acc[4][4][4];
    #pragma unroll
    for (int mt = 0; mt < 4; mt++)
        #pragma unroll
        for (int nt = 0; nt < 4; nt++)
            #pragma unroll
            for (int r = 0; r < 4; r++) acc[mt][nt][r] = 0.f;

    gemm_body(Xh, Wh, smem, acc, m0, n0);

    #pragma unroll
    for (int mt = 0; mt < 4; mt++) {
        #pragma unroll
        for (int nt = 0; nt < 4; nt++) {
            int row0 = m0 + wm * 64 + mt * 16 + g;
            int col0 = n0 + wn * 32 + nt * 8 + t4 * 2;
            #pragma unroll
            for (int r = 0; r < 4; r++) {
                int row = row0 + (r >> 1) * 8;
                int col = col0 + (r & 1);
                Y[(size_t)row * DD + col] = acc[mt][nt][r] + bias[col];
            }
        }
    }
}

// ---------------------------------------------------------------------------
// Flash attention, fp16 m16n8k16.
// Block = 8 warps; BM=128 queries (16/warp), BN=64 keys/iter, HD=64.
// S: Q A-frags (ldmatrix) x K B-frags (ldmatrix non-trans on [key][hd]).
// P: C-frag -> A-frag via pack_h2 identity (no shuffles).
// O: V B-frags via ldmatrix.trans on [key][hd].
// ---------------------------------------------------------------------------
struct AttnSmem {
    union {
        __half q[128][72];
        struct {
            __half k[64][72];
            __half v[64][72];
        } kv;
    } u;
    float mbias[64];
};

__global__ void __launch_bounds__(256, 2) attn_mma(
    const __half* __restrict__ Q, const __half* __restrict__ Kp,
    const __half* __restrict__ V, const int* __restrict__ mask,
    __half* __restrict__ ctx)
{
    __shared__ AttnSmem sm;

    const int tid  = threadIdx.x;
    const int warp = tid >> 5;
    const int lane = tid & 31;
    const int g    = lane >> 2;
    const int t4   = lane & 3;
    const int bh   = blockIdx.y;
    const int b    = bh >> 4;
    const int h    = bh & 15;
    const int s0   = blockIdx.x << 7;

    const __half* Qb = Q  + (size_t)bh * SS * HD;
    const __half* Kb = Kp + (size_t)bh * SS * HD;
    const __half* Vb = V  + (size_t)bh * SS * HD;
    const int*    mb = mask + b * SS;

    // ---- Load Q tile [128 x 64] halves ----
    #pragma unroll
    for (int i = 0; i < 4; i++) {
        int idx = tid + i * 256;          // 0..1023 uint4 (8 halves each)
        int row = idx >> 3;
        int c   = idx & 7;
        *(uint4*)&sm.u.q[row][c * 8] =
            *(const uint4*)(Qb + (size_t)(s0 + row) * HD + c * 8);
    }
    __syncthreads();

    // ---- Extract Q A-frags (persistent, 4 k-steps of 16) ----
    unsigned Qa[4][4];
    {
        unsigned q0 = (unsigned)__cvta_generic_to_shared(&sm.u.q[0][0]);
        unsigned qBase = q0 + (unsigned)((warp * 16 + (lane & 15)) * 144 + (lane >> 4) * 16);
        #pragma unroll
        for (int kt = 0; kt < 4; kt++)
            ldsm_x4(Qa[kt], qBase + (unsigned)(kt * 32));
    }
    __syncthreads();   // Q region freed before K/V overwrite

    // per-warp smem bases for K (non-trans) and V (trans)
    unsigned kBase0, vBase0;
    {
        unsigned k0 = (unsigned)__cvta_generic_to_shared(&sm.u.kv.k[0][0]);
        unsigned v0 = (unsigned)__cvta_generic_to_shared(&sm.u.kv.v[0][0]);
        kBase0 = k0 + (unsigned)((lane & 7) * 144 + (lane >> 3) * 16);
        vBase0 = v0 + (unsigned)((((lane & 7) + ((lane >> 3) & 1) * 8)) * 144 + (lane >> 4) * 16);
    }

    float Oc[8][4];
    #pragma unroll
    for (int nt = 0; nt < 8; nt++)
        #pragma unroll
        for (int r = 0; r < 4; r++) Oc[nt][r] = 0.f;
    float m0r = -1e30f, m1r = -1e30f, l0r = 0.f, l1r = 0.f;

    for (int t0 = 0; t0 < SS; t0 += 64) {
        // ---- Load K/V tiles [64 x 64] halves ----
        #pragma unroll
        for (int i = 0; i < 2; i++) {
            int idx = tid + i * 256;      // 0..511
            int row = idx >> 3;
            int c   = idx & 7;
            *(uint4*)&sm.u.kv.k[row][c * 8] =
                *(const uint4*)(Kb + (size_t)(t0 + row) * HD + c * 8);
            *(uint4*)&sm.u.kv.v[row][c * 8] =
                *(const uint4*)(Vb + (size_t)(t0 + row) * HD + c * 8);
        }
        if (tid < 64) sm.mbias[tid] = (mb[t0 + tid] == 0) ? -1e30f : 0.f;
        __syncthreads();

        // ---- S = Q . K'^T ----
        float s[8][4];
        #pragma unroll
        for (int nt = 0; nt < 8; nt++) {
            s[nt][0] = s[nt][1] = s[nt][2] = s[nt][3] = 0.f;
            unsigned kb = kBase0 + (unsigned)(nt * 8 * 144);
            unsigned r0[4], r1[4];
            ldsm_x4(r0, kb);          // k 0..31
            ldsm_x4(r1, kb + 64);     // k 32..63
            { unsigned bf[2] = { r0[0], r0[1] }; mma_f16(s[nt], Qa[0], bf); }
            { unsigned bf[2] = { r0[2], r0[3] }; mma_f16(s[nt], Qa[1], bf); }
            { unsigned bf[2] = { r1[0], r1[1] }; mma_f16(s[nt], Qa[2], bf); }
            { unsigned bf[2] = { r1[2], r1[3] }; mma_f16(s[nt], Qa[3], bf); }
            float mb0 = sm.mbias[nt * 8 + 2 * t4];
            float mb1 = sm.mbias[nt * 8 + 2 * t4 + 1];
            s[nt][0] += mb0; s[nt][1] += mb1;
            s[nt][2] += mb0; s[nt][3] += mb1;
        }

        // ---- Online softmax (rows g, g+8) ----
        float mx0 = -1e30f, mx1 = -1e30f;
        #pragma unroll
        for (int nt = 0; nt < 8; nt++) {
            mx0 = fmaxf(mx0, fmaxf(s[nt][0], s[nt][1]));
            mx1 = fmaxf(mx1, fmaxf(s[nt][2], s[nt][3]));
        }
        mx0 = fmaxf(mx0, __shfl_xor_sync(0xffffffffu, mx0, 1));
        mx0 = fmaxf(mx0, __shfl_xor_sync(0xffffffffu, mx0, 2));
        mx1 = fmaxf(mx1, __shfl_xor_sync(0xffffffffu, mx1, 1));
        mx1 = fmaxf(mx1, __shfl_xor_sync(0xffffffffu, mx1, 2));

        float nm0 = fmaxf(m0r, mx0);
        float nm1 = fmaxf(m1r, mx1);
        float al0 = __expf(m0r - nm0);
        float al1 = __expf(m1r - nm1);
        m0r = nm0; m1r = nm1;

        float rs0 = 0.f, rs1 = 0.f;
        #pragma unroll
        for (int nt = 0; nt < 8; nt++) {
            s[nt][0] = __expf(s[nt][0] - nm0);
            s[nt][1] = __expf(s[nt][1] - nm0);
            s[nt][2] = __expf(s[nt][2] - nm1);
            s[nt][3] = __expf(s[nt][3] - nm1);
            rs0 += s[nt][0] + s[nt][1];
            rs1 += s[nt][2] + s[nt][3];
        }
        rs0 += __shfl_xor_sync(0xffffffffu, rs0, 1);
        rs0 += __shfl_xor_sync(0xffffffffu, rs0, 2);
        rs1 += __shfl_xor_sync(0xffffffffu, rs1, 1);
        rs1 += __shfl_xor_sync(0xffffffffu, rs1, 2);
        l0r = l0r * al0 + rs0;
        l1r = l1r * al1 + rs1;

        #pragma unroll
        for (int nt = 0; nt < 8; nt++) {
            Oc[nt][0] *= al0; Oc[nt][1] *= al0;
            Oc[nt][2] *= al1; Oc[nt][3] *= al1;
        }

        // ---- O += P @ V : C-frag -> A-frag via pack identity ----
        #pragma unroll
        for (int kt = 0; kt < 4; kt++) {
            unsigned aP[4];
            aP[0] = pack_h2(s[2*kt  ][0], s[2*kt  ][1]);
            aP[1] = pack_h2(s[2*kt  ][2], s[2*kt  ][3]);
            aP[2] = pack_h2(s[2*kt+1][0], s[2*kt+1][1]);
            aP[3] = pack_h2(s[2*kt+1][2], s[2*kt+1][3]);
            unsigned vb = vBase0 + (unsigned)(kt * 16 * 144);
            #pragma unroll
            for (int np = 0; np < 4; np++) {
                unsigned r[4];
                ldsm_x4_trans(r, vb + (unsigned)(np * 32));
                { unsigned bf[2] = { r[0], r[1] }; mma_f16(Oc[2*np  ], aP, bf); }
                { unsigned bf[2] = { r[2], r[3] }; mma_f16(Oc[2*np+1], aP, bf); }
            }
        }
        __syncthreads();
    }

    // ---- Write ctx [B,S,D] fp16 ----
    const float inv0 = 1.0f / l0r;
    const float inv1 = 1.0f / l1r;
    const int r0 = s0 + warp * 16 + g;
    #pragma unroll
    for (int nt = 0; nt < 8; nt++) {
        int col = h * 64 + nt * 8 + 2 * t4;
        unsigned o0 = pack_h2(Oc[nt][0] * inv0, Oc[nt][1] * inv0);
        unsigned o1 = pack_h2(Oc[nt][2] * inv1, Oc[nt][3] * inv1);
        *(unsigned*)(ctx + ((size_t)b * SS + r0    ) * DD + col) = o0;
        *(unsigned*)(ctx + ((size_t)b * SS + r0 + 8) * DD + col) = o1;
    }
}

// ---------------------------------------------------------------------------

extern "C" void kernel_launch(void* const* d_in, const int* in_sizes, int n_in,
                              void* d_out, int out_size) {
    const float* x    = (const float*)d_in[0];
    const float* rel  = (const float*)d_in[1];
    const int*   mask = (const int*)  d_in[2];
    const float* Wq   = (const float*)d_in[3];
    const float* bq   = (const float*)d_in[4];
    const float* Wk   = (const float*)d_in[5];
    const float* bk   = (const float*)d_in[6];
    const float* Wv   = (const float*)d_in[7];
    const float* bv   = (const float*)d_in[8];
    const float* Wo   = (const float*)d_in[9];
    const float* bo   = (const float*)d_in[10];
    float* out = (float*)d_out;

    __half *dQh, *dKh, *dVh, *dXh, *dWh, *dCtxh;
    cudaGetSymbolAddress((void**)&dQh,   g_Qh);
    cudaGetSymbolAddress((void**)&dKh,   g_Kh);
    cudaGetSymbolAddress((void**)&dVh,   g_Vh);
    cudaGetSymbolAddress((void**)&dXh,   g_xh);
    cudaGetSymbolAddress((void**)&dWh,   g_wh);
    cudaGetSymbolAddress((void**)&dCtxh, g_ctxh);

    cudaFuncSetAttribute(gemm_qkv, cudaFuncAttributeMaxDynamicSharedMemorySize,
                         NSTAGE * STAGE_BYTES);
    cudaFuncSetAttribute(gemm_out, cudaFuncAttributeMaxDynamicSharedMemorySize,
                         NSTAGE * STAGE_BYTES);

    f2h_x<<<(MROWS * DD / 4) / 256, 256>>>((const float4*)x, dXh);
    f2h_w<<<dim3((DD * DD / 4) / 256, 4), 256>>>(
        (const float4*)Wq, (const float4*)Wk, (const float4*)Wv, (const float4*)Wo, dWh);

    gemm_qkv<<<dim3(DD / 128, MROWS / 128, 3), 256, NSTAGE * STAGE_BYTES>>>(
        dXh, dWh, bq, bk, bv, rel, dQh, dKh, dVh);

    attn_mma<<<dim3(SS / 128, BB * HH), 256>>>(dQh, dKh, dVh, mask, dCtxh);

    gemm_out<<<dim3(DD / 128, MROWS / 128), 256, NSTAGE * STAGE_BYTES>>>(
        dCtxh, dWh + (size_t)3 * DD * DD, bo, out);
}